// round 11
// baseline (speedup 1.0000x reference)
#include <cuda_runtime.h>

#define BATCH 8
#define HH 384
#define WW 384
#define PHI 32
#define RHO 64
#define NSEG 16
#define RPS (HH / NSEG)   /* 24 rows per segment, divisible by 3 */
#define GCH 8             /* channels per thread */
#define NGRP (RHO / GCH)  /* 8 channel groups */

// out[p,c] = relu( (1/9) * sum_{n in 3x3} U[q_n][c] + b3[c] )
// with U[v] = (relu(v*w1+b1) @ w2 + b2) @ w3 and q = floor(x*255/32) in {0..7}.
__global__ void __launch_bounds__(128, 8)
lpmp_deepset_kernel(const float* __restrict__ x,  const float* __restrict__ w1,
                    const float* __restrict__ b1, const float* __restrict__ w2,
                    const float* __restrict__ b2, const float* __restrict__ w3,
                    const float* __restrict__ b3, float* __restrict__ out)
{
    __shared__ __align__(16) float Tsh[8][33];  // T[q][k] = b2[k] + sum_j relu(q*w1[j]+b1[j])*w2[j][k]
    __shared__ __align__(16) float U1[8][8];    // U'[q][c] for this block's 8 channels, scaled 1/9

    const int tid   = threadIdx.x;
    const int xtile = blockIdx.x;
    const int b     = blockIdx.y / NSEG;
    const int seg   = blockIdx.y % NSEG;
    const int g     = blockIdx.z;

    // ---- build the 8-entry table (tiny prologue) ----
    #pragma unroll
    for (int e = tid; e < 8 * PHI; e += 128) {
        const int q = e >> 5, k = e & 31;
        const float fq = (float)q;
        float acc = b2[k];
        #pragma unroll
        for (int j = 0; j < PHI; j++) {
            float hv = fmaxf(fmaf(fq, w1[j], b1[j]), 0.0f);
            acc = fmaf(hv, w2[j * PHI + k], acc);
        }
        Tsh[q][k] = acc;
    }
    __syncthreads();
    if (tid < 64) {
        const int q = tid >> 3, c = tid & 7;    // 64 threads == 8*8 entries
        float acc = 0.0f;
        #pragma unroll
        for (int k = 0; k < PHI; k++)
            acc = fmaf(Tsh[q][k], w3[k * RHO + g * GCH + c], acc);
        U1[q][c] = acc * (1.0f / 9.0f);
    }
    __syncthreads();

    float b3r[GCH];
    #pragma unroll
    for (int c = 0; c < GCH; c++) b3r[c] = b3[g * GCH + c];

    const int x0 = xtile * 128 + tid;                  // this thread's column
    const float* __restrict__ xin = x + b * (HH * WW);
    float* __restrict__ ob = out + ((size_t)(b * RHO + g * GCH)) * (HH * WW) + x0;

    const float QS = 255.0f / 32.0f;
    const int y0 = seg * RPS;

    float R[3][GCH];

    // Row sum of table entries for columns x0-1, x0, x0+1 at row yy.
    auto rowsum = [&](int yy, float* __restrict__ N) {
        int c0 = 0, c1 = 0, c2 = 0;
        if (yy >= 0 && yy < HH) {
            const float* row = xin + yy * WW;
            float v1 = __ldg(row + x0);
            float v0 = (x0 > 0)      ? __ldg(row + x0 - 1) : 0.0f;
            float v2 = (x0 < WW - 1) ? __ldg(row + x0 + 1) : 0.0f;
            // values are >= 0 so int-cast == floor; clamp guards shared OOB
            c0 = min((int)(v0 * QS), 7);
            c1 = min((int)(v1 * QS), 7);
            c2 = min((int)(v2 * QS), 7);
        }
        const float4* p0 = (const float4*)(&U1[c0][0]);
        const float4* p1 = (const float4*)(&U1[c1][0]);
        const float4* p2 = (const float4*)(&U1[c2][0]);
        #pragma unroll
        for (int v = 0; v < 2; v++) {
            float4 a = p0[v], bb = p1[v], cc = p2[v];
            N[4 * v + 0] = a.x + bb.x + cc.x;
            N[4 * v + 1] = a.y + bb.y + cc.y;
            N[4 * v + 2] = a.z + bb.z + cc.z;
            N[4 * v + 3] = a.w + bb.w + cc.w;
        }
    };

    rowsum(y0 - 1, R[0]);
    rowsum(y0,     R[1]);

    for (int y = y0; y < y0 + RPS; y += 3) {
        #pragma unroll
        for (int k = 0; k < 3; k++) {
            const int yy = y + k;
            float* P = R[k];
            float* C = R[(k + 1) % 3];
            float* N = R[(k + 2) % 3];
            rowsum(yy + 1, N);
            float* orow = ob + yy * WW;
            #pragma unroll
            for (int c = 0; c < GCH; c++) {
                float s = fmaxf(P[c] + C[c] + N[c] + b3r[c], 0.0f);
                orow[c * (HH * WW)] = s;
            }
        }
    }
}

extern "C" void kernel_launch(void* const* d_in, const int* in_sizes, int n_in,
                              void* d_out, int out_size) {
    const float* x  = (const float*)d_in[0];
    const float* w1 = (const float*)d_in[1];
    const float* b1 = (const float*)d_in[2];
    const float* w2 = (const float*)d_in[3];
    const float* b2 = (const float*)d_in[4];
    const float* w3 = (const float*)d_in[5];
    const float* b3 = (const float*)d_in[6];
    float* out = (float*)d_out;

    dim3 grid(WW / 128, BATCH * NSEG, NGRP);
    lpmp_deepset_kernel<<<grid, 128>>>(x, w1, b1, w2, b2, w3, b3, out);
}

// round 14
// speedup vs baseline: 1.0317x; 1.0317x over previous
#include <cuda_runtime.h>
#include <cstdint>

#define BATCH 8
#define HH 384
#define WW 384
#define PHI 32
#define RHO 64
#define NSEG 16
#define RPS (HH / NSEG)   /* 24 rows per segment, divisible by 3 */
#define GCH 8             /* channels per thread */
#define NGRP (RHO / GCH)  /* 8 channel groups */
#define PLANE (HH * WW)

// Packed f32x2 add (sm_103a). Two fp32 adds per issue slot.
__device__ __forceinline__ uint64_t addp(uint64_t a, uint64_t b) {
    uint64_t r;
    asm("add.rn.f32x2 %0, %1, %2;" : "=l"(r) : "l"(a), "l"(b));
    return r;
}

#define LDS_V2U64(r0, r1, a) \
    asm volatile("ld.shared.v2.u64 {%0, %1}, [%2];" : "=l"(r0), "=l"(r1) : "r"(a))

#define UNPK(lo, hi, v) \
    asm("mov.b64 {%0, %1}, %2;" : "=f"(lo), "=f"(hi) : "l"(v))

__device__ __forceinline__ uint32_t smem_u32(const void* p) {
    uint32_t a;
    asm("{ .reg .u64 t; cvta.to.shared.u64 t, %1; cvt.u32.u64 %0, t; }"
        : "=r"(a) : "l"(p));
    return a;
}

// out[p,c] = relu( sum_{n in 3x3} U1[q_n][c] ),  U1[v][c] = (U[v][c] + b3[c]) / 9
// with U[v] = (relu(v*w1+b1) @ w2 + b2) @ w3 and q = floor(x*255/32) in {0..7}.
__global__ void __launch_bounds__(128, 8)
lpmp_deepset_kernel(const float* __restrict__ x,  const float* __restrict__ w1,
                    const float* __restrict__ b1, const float* __restrict__ w2,
                    const float* __restrict__ b2, const float* __restrict__ w3,
                    const float* __restrict__ b3, float* __restrict__ out)
{
    __shared__ __align__(16) float Tsh[8][33];  // T[q][k] = b2[k] + sum_j relu(q*w1[j]+b1[j])*w2[j][k]
    __shared__ __align__(16) float U1[8][8];    // bias-folded, 1/9-scaled LUT; row = 32B

    const int tid   = threadIdx.x;
    const int xtile = blockIdx.x;
    const int b     = blockIdx.y / NSEG;
    const int seg   = blockIdx.y % NSEG;
    const int g     = blockIdx.z;

    // ---- build the 8-entry table (tiny prologue) ----
    #pragma unroll
    for (int e = tid; e < 8 * PHI; e += 128) {
        const int q = e >> 5, k = e & 31;
        const float fq = (float)q;
        float acc = b2[k];
        #pragma unroll
        for (int j = 0; j < PHI; j++) {
            float hv = fmaxf(fmaf(fq, w1[j], b1[j]), 0.0f);
            acc = fmaf(hv, w2[j * PHI + k], acc);
        }
        Tsh[q][k] = acc;
    }
    __syncthreads();
    if (tid < 64) {
        const int q = tid >> 3, c = tid & 7;    // 64 threads == 8*8 entries
        float acc = 0.0f;
        #pragma unroll
        for (int k = 0; k < PHI; k++)
            acc = fmaf(Tsh[q][k], w3[k * RHO + g * GCH + c], acc);
        U1[q][c] = (acc + b3[g * GCH + c]) * (1.0f / 9.0f);  // bias folded: mean + b3 == sum of (U+b3)/9
    }
    __syncthreads();

    const uint32_t u1base = smem_u32(&U1[0][0]);

    const int x0 = xtile * 128 + tid;                  // this thread's column
    const float* __restrict__ xin = x + b * PLANE;
    float* __restrict__ ob = out + ((size_t)(b * RHO + g * GCH)) * PLANE + x0;

    const float QS = 255.0f / 32.0f;
    const int y0 = seg * RPS;

    uint64_t R[3][4];   // 3-row sliding window of packed f32x2 row-sums (8 ch = 4 pairs)

    // Row sum of table entries for columns x0-1, x0, x0+1 at row yy (packed).
    auto rowsum = [&](int yy, uint64_t* __restrict__ N) {
        uint32_t a0 = 0, a1 = 0, a2 = 0;       // byte offsets into U1 (row = 32B)
        if (yy >= 0 && yy < HH) {
            const float* row = xin + yy * WW;
            float v1 = __ldg(row + x0);
            float v0 = (x0 > 0)      ? __ldg(row + x0 - 1) : 0.0f;
            float v2 = (x0 < WW - 1) ? __ldg(row + x0 + 1) : 0.0f;
            // x in [0,1) => v*QS < 7.96875 => floor in [0,7]; trunc == floor for v>=0
            a0 = ((uint32_t)(int)(v0 * QS)) << 5;
            a1 = ((uint32_t)(int)(v1 * QS)) << 5;
            a2 = ((uint32_t)(int)(v2 * QS)) << 5;
        }
        uint64_t A0, A1, A2, A3, B0, B1, B2, B3, C0, C1, C2, C3;
        LDS_V2U64(A0, A1, u1base + a0);  LDS_V2U64(A2, A3, u1base + a0 + 16);
        LDS_V2U64(B0, B1, u1base + a1);  LDS_V2U64(B2, B3, u1base + a1 + 16);
        LDS_V2U64(C0, C1, u1base + a2);  LDS_V2U64(C2, C3, u1base + a2 + 16);
        N[0] = addp(addp(A0, B0), C0);
        N[1] = addp(addp(A1, B1), C1);
        N[2] = addp(addp(A2, B2), C2);
        N[3] = addp(addp(A3, B3), C3);
    };

    rowsum(y0 - 1, R[0]);
    rowsum(y0,     R[1]);

    for (int y = y0; y < y0 + RPS; y += 3) {
        #pragma unroll
        for (int k = 0; k < 3; k++) {
            const int yy = y + k;
            uint64_t* P = R[k];
            uint64_t* C = R[(k + 1) % 3];
            uint64_t* N = R[(k + 2) % 3];
            rowsum(yy + 1, N);
            float* orow = ob + yy * WW;
            #pragma unroll
            for (int j = 0; j < 4; j++) {
                uint64_t s = addp(addp(P[j], C[j]), N[j]);
                float lo, hi;
                UNPK(lo, hi, s);
                orow[(2 * j + 0) * PLANE] = fmaxf(lo, 0.0f);
                orow[(2 * j + 1) * PLANE] = fmaxf(hi, 0.0f);
            }
        }
    }
}

extern "C" void kernel_launch(void* const* d_in, const int* in_sizes, int n_in,
                              void* d_out, int out_size) {
    const float* x  = (const float*)d_in[0];
    const float* w1 = (const float*)d_in[1];
    const float* b1 = (const float*)d_in[2];
    const float* w2 = (const float*)d_in[3];
    const float* b2 = (const float*)d_in[4];
    const float* w3 = (const float*)d_in[5];
    const float* b3 = (const float*)d_in[6];
    float* out = (float*)d_out;

    dim3 grid(WW / 128, BATCH * NSEG, NGRP);
    lpmp_deepset_kernel<<<grid, 128>>>(x, w1, b1, w2, b2, w3, b3, out);
}